// round 5
// baseline (speedup 1.0000x reference)
#include <cuda_runtime.h>

#define NN 50000
#define NE 800000
#define D  128
#define NBLK 98            // ceil(50000/512)

// ---- scratch (no allocations allowed) ----
__device__ int   g_src[NE];
__device__ int   g_dst[NE];
__device__ int   g_deg[NN];
__device__ int   g_rowptr[NN + 1];
__device__ int   g_cursor[NN];
__device__ int   g_csr[NE];     // source node per CSR slot (grouped by dst)
__device__ float g_csw[NE];     // dis[src] per CSR slot
__device__ float g_dis[NN];
__device__ float g_h[NN * D];   // GEMM output (both layers)
__device__ float g_x1[NN * D];  // layer-1 activation
__device__ int   g_bsum[128];
__device__ int   g_is64;

// zero deg + dtype-detect (int64 ids < 2^31 -> all odd 32-bit words are 0)
__global__ void k_zero_detect(const int* __restrict__ ei32) {
    int i = blockIdx.x * blockDim.x + threadIdx.x;
    if (i < NN) g_deg[i] = 0;
    if (blockIdx.x == 0 && threadIdx.x < 32) {
        int lane = threadIdx.x;
        int acc = 0;
        for (int j = 0; j < 8; j++) acc |= ei32[1 + 2 * (lane + 32 * j)];
        unsigned b = __ballot_sync(0xFFFFFFFFu, acc != 0);
        if (lane == 0) g_is64 = (b == 0) ? 1 : 0;
    }
}

__global__ void k_prep(const void* __restrict__ eiv) {
    int e = blockIdx.x * blockDim.x + threadIdx.x;
    if (e >= NE) return;
    int s, d;
    if (g_is64) {
        const long long* ei = (const long long*)eiv;
        s = (int)ei[e];
        d = (int)ei[NE + e];
    } else {
        const int* ei = (const int*)eiv;
        s = ei[e];
        d = ei[NE + e];
    }
    if ((unsigned)s >= NN) s = 0;
    if ((unsigned)d >= NN) d = 0;
    g_src[e] = s;
    g_dst[e] = d;
    atomicAdd(&g_deg[d], 1);
}

// dis = rsqrt(deg+1) fused with per-block degree partial sums
__global__ void k_dis_partsum() {
    __shared__ int sh[512];
    int t = threadIdx.x;
    int i = blockIdx.x * 512 + t;
    int dg = 0;
    if (i < NN) {
        dg = g_deg[i];
        g_dis[i] = rsqrtf((float)(dg + 1));
    }
    sh[t] = dg;
    __syncthreads();
    for (int o = 256; o > 0; o >>= 1) {
        if (t < o) sh[t] += sh[t + o];
        __syncthreads();
    }
    if (t == 0) g_bsum[blockIdx.x] = sh[0];
}

__global__ void k_scanb() {  // 1 block: exclusive scan of NBLK block sums
    __shared__ int sh[128];
    int t = threadIdx.x;
    int v = (t < NBLK) ? g_bsum[t] : 0;
    sh[t] = v;
    __syncthreads();
    for (int o = 1; o < 128; o <<= 1) {
        int a = (t >= o) ? sh[t - o] : 0;
        __syncthreads();
        sh[t] += a;
        __syncthreads();
    }
    if (t < NBLK) g_bsum[t] = sh[t] - v;   // exclusive
}

__global__ void k_rowptr() {
    __shared__ int sh[512];
    int t = threadIdx.x;
    int i = blockIdx.x * 512 + t;
    int v = (i < NN) ? g_deg[i] : 0;
    sh[t] = v;
    __syncthreads();
    for (int o = 1; o < 512; o <<= 1) {
        int a = (t >= o) ? sh[t - o] : 0;
        __syncthreads();
        sh[t] += a;
        __syncthreads();
    }
    if (i < NN) {
        int ex = g_bsum[blockIdx.x] + sh[t] - v;
        g_rowptr[i] = ex;
        g_cursor[i] = ex;
    }
    if (i == 0) g_rowptr[NN] = NE;
}

__global__ void k_fill() {
    int e = blockIdx.x * blockDim.x + threadIdx.x;
    if (e >= NE) return;
    int d = g_dst[e];
    int s = g_src[e];
    int pos = atomicAdd(&g_cursor[d], 1);
    if ((unsigned)pos < NE) {
        g_csr[pos] = s;
        g_csw[pos] = g_dis[s];
    }
}

// ---- packed f32x2 helpers ----
__device__ __forceinline__ unsigned long long pack2(float v) {
    unsigned long long r;
    asm("mov.b64 %0, {%1, %1};" : "=l"(r) : "f"(v));
    return r;
}
__device__ __forceinline__ void ffma2(unsigned long long& d,
                                      unsigned long long a,
                                      unsigned long long b) {
    asm("fma.rn.f32x2 %0, %1, %2, %0;" : "+l"(d) : "l"(a), "l"(b));
}

// GEMM: g_h[NN,128] = x[NN,128] @ W[128,128], packed f32x2 FFMA.
// block 256 thr, tile 64 rows. warp -> 8 rows; lane&15 -> 8-col group,
// lane>>4 -> row-half. Each thread: 4 rows x 8 cols (16 b64 accumulators).
__global__ void k_gemm(const float* __restrict__ x_ext, const float* __restrict__ W,
                       int use_x1) {
    const float* x = use_x1 ? g_x1 : x_ext;
    __shared__ float xs[64 * 128];
    int t    = threadIdx.x;
    int base = blockIdx.x * 64;

    const float4* x4  = (const float4*)x;
    float4*       xs4 = (float4*)xs;
    for (int i = t; i < 64 * 32; i += 256) {
        int r = i >> 5, ci = i & 31;
        int g = base + r;
        float4 v = make_float4(0.f, 0.f, 0.f, 0.f);
        if (g < NN) v = x4[g * 32 + ci];
        xs4[i] = v;
    }
    __syncthreads();

    int wid  = t >> 5;
    int lane = t & 31;
    int c    = lane & 15;           // 8-col group: cols [c*8, c*8+8)
    int half = lane >> 4;           // row half within warp
    int r0   = wid * 8 + half * 4;  // local row base (4 rows)

    const ulonglong2* Wu2 = (const ulonglong2*)W;

    unsigned long long acc[4][4];
#pragma unroll
    for (int r = 0; r < 4; r++)
#pragma unroll
        for (int j = 0; j < 4; j++) acc[r][j] = 0ull;

    for (int k0 = 0; k0 < 128; k0 += 4) {
        float xa[4][4];
#pragma unroll
        for (int r = 0; r < 4; r++) {
            float4 xv = *(const float4*)&xs[(r0 + r) * 128 + k0];
            xa[r][0] = xv.x; xa[r][1] = xv.y; xa[r][2] = xv.z; xa[r][3] = xv.w;
        }
#pragma unroll
        for (int kk = 0; kk < 4; kk++) {
            ulonglong2 wA = Wu2[(k0 + kk) * 32 + c * 2];
            ulonglong2 wB = Wu2[(k0 + kk) * 32 + c * 2 + 1];
#pragma unroll
            for (int r = 0; r < 4; r++) {
                unsigned long long xp = pack2(xa[r][kk]);
                ffma2(acc[r][0], xp, wA.x);
                ffma2(acc[r][1], xp, wA.y);
                ffma2(acc[r][2], xp, wB.x);
                ffma2(acc[r][3], xp, wB.y);
            }
        }
    }

    float4* out4 = (float4*)g_h;
#pragma unroll
    for (int r = 0; r < 4; r++) {
        int g = base + r0 + r;
        if (g < NN) {
            union { unsigned long long u[2]; float4 f; } o;
            o.u[0] = acc[r][0]; o.u[1] = acc[r][1];
            out4[g * 32 + c * 2] = o.f;
            o.u[0] = acc[r][2]; o.u[1] = acc[r][3];
            out4[g * 32 + c * 2 + 1] = o.f;
        }
    }
}

// Aggregation: one warp per node, lane holds 4 contiguous columns (float4).
// out[d] = dis[d] * sum_e( dis[src_e] * h[src_e] ) + dis[d]^2 * h[d] + bias
// Edge loop unrolled x2 with independent partial sums for MLP=2 on L2 gathers.
__global__ void k_agg(const float* __restrict__ bias, float* __restrict__ out_ext,
                      int layer) {
    int node = blockIdx.x * (blockDim.x >> 5) + (threadIdx.x >> 5);
    if (node >= NN) return;
    int lane = threadIdx.x & 31;

    int beg = g_rowptr[node];
    int end = g_rowptr[node + 1];

    const float4* h4 = (const float4*)g_h;
    float4 acc0 = make_float4(0.f, 0.f, 0.f, 0.f);
    float4 acc1 = make_float4(0.f, 0.f, 0.f, 0.f);

    int e = beg;
    for (; e + 1 < end; e += 2) {
        int   s0 = g_csr[e];
        int   s1 = g_csr[e + 1];
        float c0 = g_csw[e];
        float c1 = g_csw[e + 1];
        float4 v0 = h4[s0 * 32 + lane];
        float4 v1 = h4[s1 * 32 + lane];
        acc0.x = fmaf(c0, v0.x, acc0.x);
        acc0.y = fmaf(c0, v0.y, acc0.y);
        acc0.z = fmaf(c0, v0.z, acc0.z);
        acc0.w = fmaf(c0, v0.w, acc0.w);
        acc1.x = fmaf(c1, v1.x, acc1.x);
        acc1.y = fmaf(c1, v1.y, acc1.y);
        acc1.z = fmaf(c1, v1.z, acc1.z);
        acc1.w = fmaf(c1, v1.w, acc1.w);
    }
    if (e < end) {
        int   s0 = g_csr[e];
        float c0 = g_csw[e];
        float4 v0 = h4[s0 * 32 + lane];
        acc0.x = fmaf(c0, v0.x, acc0.x);
        acc0.y = fmaf(c0, v0.y, acc0.y);
        acc0.z = fmaf(c0, v0.z, acc0.z);
        acc0.w = fmaf(c0, v0.w, acc0.w);
    }
    acc0.x += acc1.x; acc0.y += acc1.y; acc0.z += acc1.z; acc0.w += acc1.w;

    float dn = g_dis[node];
    float sn = dn * dn;
    float4 hv = h4[node * 32 + lane];
    float4 b  = ((const float4*)bias)[lane];

    float4 r;
    r.x = dn * acc0.x + sn * hv.x + b.x;
    r.y = dn * acc0.y + sn * hv.y + b.y;
    r.z = dn * acc0.z + sn * hv.z + b.z;
    r.w = dn * acc0.w + sn * hv.w + b.w;

    if (layer == 0) {
        r.x = fmaxf(r.x, 0.f);
        r.y = fmaxf(r.y, 0.f);
        r.z = fmaxf(r.z, 0.f);
        r.w = fmaxf(r.w, 0.f);
        ((float4*)g_x1)[node * 32 + lane] = r;
    } else {
        ((float4*)out_ext)[node * 32 + lane] = r;
    }
}

extern "C" void kernel_launch(void* const* d_in, const int* in_sizes, int n_in,
                              void* d_out, int out_size) {
    const void*  ei  = d_in[0];
    const float* emb = (const float*)d_in[1];
    const float* W1  = (const float*)d_in[2];
    const float* b1  = (const float*)d_in[3];
    const float* W2  = (const float*)d_in[4];
    const float* b2  = (const float*)d_in[5];
    float* out = (float*)d_out;

    (void)in_sizes; (void)n_in; (void)out_size;

    // ---- graph preprocessing ----
    k_zero_detect<<<(NN + 255) / 256, 256>>>((const int*)ei);
    k_prep<<<(NE + 255) / 256, 256>>>(ei);
    k_dis_partsum<<<NBLK, 512>>>();
    k_scanb<<<1, 128>>>();
    k_rowptr<<<NBLK, 512>>>();
    k_fill<<<(NE + 255) / 256, 256>>>();

    // ---- layer 1 ----
    k_gemm<<<(NN + 63) / 64, 256>>>(emb, W1, 0);
    k_agg<<<(NN + 7) / 8, 256>>>(b1, out, 0);   // writes g_x1 (relu)

    // ---- layer 2 ----
    k_gemm<<<(NN + 63) / 64, 256>>>(nullptr, W2, 1);
    k_agg<<<(NN + 7) / 8, 256>>>(b2, out, 1);   // writes d_out
}

// round 8
// speedup vs baseline: 1.0814x; 1.0814x over previous
#include <cuda_runtime.h>

#define NN 50000
#define NE 800000
#define D  128
#define NBLK 98                       // ceil(50000/512) for scan kernel
#define GEMM_BLKS 1563                // ceil(50000/32)
#define PREP_BLKS 782                 // 782*256 = 200192 threads, 4 edges each
#define PREP_THREADS (PREP_BLKS * 256)

// ---- scratch (no allocations allowed) ----
__device__ int   g_deg[NN];
__device__ int   g_rowptr[NN + 1];
__device__ int   g_cursor[NN];
__device__ int   g_srcd[NE];      // staged src
__device__ int   g_dstd[NE];      // staged dst
__device__ int2  g_edge[NE];      // CSR slot: {src, dis[src] bits}
__device__ float g_dis[NN];
__device__ float g_h[NN * D];     // GEMM output (both layers)
__device__ float g_x1[NN * D];    // layer-1 activation
__device__ int   g_part[NBLK];
__device__ int   g_pdone;
__device__ int   g_is64;

// zero deg + scan flag + dtype-detect (int64 ids < 2^31 -> odd 32-bit words all 0)
__global__ void k_zero_detect(const int* __restrict__ ei32) {
    int i = blockIdx.x * blockDim.x + threadIdx.x;
    if (i < NN) g_deg[i] = 0;
    if (i == 0) g_pdone = 0;
    if (blockIdx.x == 0 && threadIdx.x < 32) {
        int lane = threadIdx.x;
        int acc = 0;
        for (int j = 0; j < 8; j++) acc |= ei32[1 + 2 * (lane + 32 * j)];
        unsigned b = __ballot_sync(0xFFFFFFFFu, acc != 0);
        if (lane == 0) g_is64 = (b == 0) ? 1 : 0;
    }
}

// ---------------------------------------------------------------------------
// Phase A: blocks [0, GEMM_BLKS) do layer-1 GEMM tiles; blocks
// [GEMM_BLKS, GEMM_BLKS+PREP_BLKS) decode edges + count degrees.
// Disjoint pipes (fma vs LSU/atomic) -> prep hides under GEMM.
// ---------------------------------------------------------------------------
__device__ __forceinline__ void gemm_tile(const float* __restrict__ x,
                                          const float* __restrict__ W,
                                          float* __restrict__ out,
                                          int base, float* xs) {
    int t = threadIdx.x;
    const float4* x4  = (const float4*)x;
    float4*       xs4 = (float4*)xs;
    for (int i = t; i < 32 * 32; i += 256) {
        int r = i >> 5, c = i & 31;
        int g = base + r;
        float4 v = make_float4(0.f, 0.f, 0.f, 0.f);
        if (g < NN) v = x4[g * 32 + c];
        xs4[i] = v;
    }
    __syncthreads();

    int w = t >> 5, lane = t & 31;
    int r0 = w * 4;
    const float4* W4 = (const float4*)W;

    float4 acc[4];
#pragma unroll
    for (int r = 0; r < 4; r++) acc[r] = make_float4(0.f, 0.f, 0.f, 0.f);

    for (int k0 = 0; k0 < 128; k0 += 4) {
        float xa[4][4];
#pragma unroll
        for (int r = 0; r < 4; r++) {
            float4 xv = *(const float4*)&xs[(r0 + r) * 128 + k0];
            xa[r][0] = xv.x; xa[r][1] = xv.y; xa[r][2] = xv.z; xa[r][3] = xv.w;
        }
#pragma unroll
        for (int kk = 0; kk < 4; kk++) {
            float4 wv = W4[(k0 + kk) * 32 + lane];
#pragma unroll
            for (int r = 0; r < 4; r++) {
                acc[r].x = fmaf(xa[r][kk], wv.x, acc[r].x);
                acc[r].y = fmaf(xa[r][kk], wv.y, acc[r].y);
                acc[r].z = fmaf(xa[r][kk], wv.z, acc[r].z);
                acc[r].w = fmaf(xa[r][kk], wv.w, acc[r].w);
            }
        }
    }

    float4* out4 = (float4*)out;
#pragma unroll
    for (int r = 0; r < 4; r++) {
        int g = base + r0 + r;
        if (g < NN) out4[g * 32 + lane] = acc[r];
    }
}

__global__ void k_gemm1_prep(const float* __restrict__ emb,
                             const float* __restrict__ W1,
                             const void* __restrict__ eiv) {
    __shared__ float xs[32 * 128];
    int b = blockIdx.x;
    if (b < GEMM_BLKS) {
        gemm_tile(emb, W1, g_h, b * 32, xs);
        return;
    }
    // prep role
    int idx = (b - GEMM_BLKS) * 256 + threadIdx.x;
    int is64 = g_is64;
    const long long* ei64 = (const long long*)eiv;
    const int*       ei32 = (const int*)eiv;
    for (int e = idx; e < NE; e += PREP_THREADS) {
        int s, d;
        if (is64) {
            s = (int)ei64[e];
            d = (int)ei64[NE + e];
        } else {
            s = ei32[e];
            d = ei32[NE + e];
        }
        if ((unsigned)s >= NN) s = 0;
        if ((unsigned)d >= NN) d = 0;
        g_srcd[e] = s;
        g_dstd[e] = d;
        atomicAdd(&g_deg[d], 1);
    }
}

// ---------------------------------------------------------------------------
// Fused dis + full exclusive scan (rowptr/cursor) in ONE kernel.
// 98 blocks <= 148 SMs -> all co-resident in wave 1 -> spin is deadlock-free.
// ---------------------------------------------------------------------------
__global__ void k_scan_all() {
    __shared__ int sh[512];
    __shared__ int s_prefix;
    int t = threadIdx.x, b = blockIdx.x;
    int i = b * 512 + t;

    int dg = 0;
    if (i < NN) {
        dg = g_deg[i];
        g_dis[i] = rsqrtf((float)(dg + 1));
    }
    sh[t] = dg;
    __syncthreads();
    for (int o = 1; o < 512; o <<= 1) {
        int a = (t >= o) ? sh[t - o] : 0;
        __syncthreads();
        sh[t] += a;
        __syncthreads();
    }
    int incl = sh[t];

    if (t == 511) {
        g_part[b] = incl;            // block total
        __threadfence();
        atomicAdd(&g_pdone, 1);
    }
    if (t == 0) {
        volatile int* p = &g_pdone;
        while (*p < NBLK) {}
    }
    __syncthreads();

    if (t < 32) {
        int s = 0;
        for (int j = t; j < b; j += 32) s += __ldcg(&g_part[j]);
#pragma unroll
        for (int o = 16; o > 0; o >>= 1) s += __shfl_down_sync(0xFFFFFFFFu, s, o);
        if (t == 0) s_prefix = s;
    }
    __syncthreads();

    if (i < NN) {
        int ex = s_prefix + incl - dg;   // exclusive
        g_rowptr[i] = ex;
        g_cursor[i] = ex;
    }
    if (i == 0) g_rowptr[NN] = NE;
}

__global__ void k_fill() {
    int e = blockIdx.x * blockDim.x + threadIdx.x;
    if (e >= NE) return;
    int d = g_dstd[e];
    int s = g_srcd[e];
    int pos = atomicAdd(&g_cursor[d], 1);
    if ((unsigned)pos < NE) {
        g_edge[pos] = make_int2(s, __float_as_int(g_dis[s]));
    }
}

// plain GEMM for layer 2 (reads g_x1 -> g_h)
__global__ void k_gemm2(const float* __restrict__ W) {
    __shared__ float xs[32 * 128];
    gemm_tile(g_x1, W, g_h, blockIdx.x * 32, xs);
}

// Aggregation: one warp per node; lane holds 4 contiguous cols (float4).
// out[d] = dis[d] * sum_e( dis[src_e] * h[src_e] ) + dis[d]^2 * h[d] + bias
__global__ void k_agg(const float* __restrict__ bias, float* __restrict__ out_ext,
                      int layer) {
    int node = blockIdx.x * (blockDim.x >> 5) + (threadIdx.x >> 5);
    if (node >= NN) return;
    int lane = threadIdx.x & 31;

    int beg = g_rowptr[node];
    int end = g_rowptr[node + 1];

    const float4* h4 = (const float4*)g_h;
    float4 acc0 = make_float4(0.f, 0.f, 0.f, 0.f);
    float4 acc1 = make_float4(0.f, 0.f, 0.f, 0.f);

    int e = beg;
    for (; e + 1 < end; e += 2) {
        int2 p0 = g_edge[e];
        int2 p1 = g_edge[e + 1];
        float c0 = __int_as_float(p0.y);
        float c1 = __int_as_float(p1.y);
        float4 v0 = h4[p0.x * 32 + lane];
        float4 v1 = h4[p1.x * 32 + lane];
        acc0.x = fmaf(c0, v0.x, acc0.x);
        acc0.y = fmaf(c0, v0.y, acc0.y);
        acc0.z = fmaf(c0, v0.z, acc0.z);
        acc0.w = fmaf(c0, v0.w, acc0.w);
        acc1.x = fmaf(c1, v1.x, acc1.x);
        acc1.y = fmaf(c1, v1.y, acc1.y);
        acc1.z = fmaf(c1, v1.z, acc1.z);
        acc1.w = fmaf(c1, v1.w, acc1.w);
    }
    if (e < end) {
        int2 p0 = g_edge[e];
        float c0 = __int_as_float(p0.y);
        float4 v0 = h4[p0.x * 32 + lane];
        acc0.x = fmaf(c0, v0.x, acc0.x);
        acc0.y = fmaf(c0, v0.y, acc0.y);
        acc0.z = fmaf(c0, v0.z, acc0.z);
        acc0.w = fmaf(c0, v0.w, acc0.w);
    }
    acc0.x += acc1.x; acc0.y += acc1.y; acc0.z += acc1.z; acc0.w += acc1.w;

    float dn = g_dis[node];
    float sn = dn * dn;
    float4 hv = h4[node * 32 + lane];
    float4 b  = ((const float4*)bias)[lane];

    float4 r;
    r.x = dn * acc0.x + sn * hv.x + b.x;
    r.y = dn * acc0.y + sn * hv.y + b.y;
    r.z = dn * acc0.z + sn * hv.z + b.z;
    r.w = dn * acc0.w + sn * hv.w + b.w;

    if (layer == 0) {
        r.x = fmaxf(r.x, 0.f);
        r.y = fmaxf(r.y, 0.f);
        r.z = fmaxf(r.z, 0.f);
        r.w = fmaxf(r.w, 0.f);
        ((float4*)g_x1)[node * 32 + lane] = r;
    } else {
        ((float4*)out_ext)[node * 32 + lane] = r;
    }
}

extern "C" void kernel_launch(void* const* d_in, const int* in_sizes, int n_in,
                              void* d_out, int out_size) {
    const void*  ei  = d_in[0];
    const float* emb = (const float*)d_in[1];
    const float* W1  = (const float*)d_in[2];
    const float* b1  = (const float*)d_in[3];
    const float* W2  = (const float*)d_in[4];
    const float* b2  = (const float*)d_in[5];
    float* out = (float*)d_out;

    (void)in_sizes; (void)n_in; (void)out_size;

    k_zero_detect<<<(NN + 255) / 256, 256>>>((const int*)ei);
    k_gemm1_prep<<<GEMM_BLKS + PREP_BLKS, 256>>>(emb, W1, ei);   // gemm1 ∥ prep
    k_scan_all<<<NBLK, 512>>>();                                  // dis+scan+rowptr
    k_fill<<<(NE + 255) / 256, 256>>>();
    k_agg<<<(NN + 7) / 8, 256>>>(b1, out, 0);                     // g_x1 (relu)
    k_gemm2<<<GEMM_BLKS, 256>>>(W2);
    k_agg<<<(NN + 7) / 8, 256>>>(b2, out, 1);                     // d_out
}

// round 9
// speedup vs baseline: 1.6080x; 1.4869x over previous
#include <cuda_runtime.h>
#include <cstdint>

#define NN 50000
#define NE 800000
#define D  128
#define NBLK 98                  // ceil(50000/512) scan blocks
#define GBLK 782                 // ceil(50000/64) gemm blocks

// ---- scratch (no allocations allowed) ----
__device__ int      g_deg[NN];
__device__ int      g_rowptr[NN + 1];
__device__ int      g_cursor[NN];
__device__ int      g_srcd[NE];
__device__ int      g_dstd[NE];
__device__ int2     g_edge[NE];      // {src, dis[src] bits}
__device__ float    g_dis[NN];
__device__ float    g_h[NN * D];
__device__ float    g_x1[NN * D];
__device__ int      g_part[NBLK];
__device__ int      g_pdone;
__device__ int      g_is64;
__device__ unsigned g_wf[2][16384];  // fragment-ordered tf32 weights

__device__ __forceinline__ unsigned to_tf32(float f) {
    unsigned r;
    asm("cvt.rna.tf32.f32 %0, %1;" : "=r"(r) : "f"(f));
    return r;
}

// init: zero deg, reset scan flag, dtype-detect, build fragment-ordered tf32 W1/W2.
// wf layout: frag(kt 0..15, nt 0..15): elem = ((kt*16+nt)*32 + lane)*2 + r
//   value = tf32( W[(kt*8 + lane%4 + r*4)*128 + nt*8 + lane/4] )
__global__ void k_init(const int* __restrict__ ei32,
                       const float* __restrict__ W1,
                       const float* __restrict__ W2) {
    int i = blockIdx.x * blockDim.x + threadIdx.x;
    if (i < NN) g_deg[i] = 0;
    if (i == 0) g_pdone = 0;
    if (i < 32768) {
        int l  = (i >= 16384) ? 1 : 0;
        int j  = i & 16383;
        int r  = j & 1;
        int ln = (j >> 1) & 31;
        int nt = (j >> 6) & 15;
        int kt = j >> 10;
        int k  = kt * 8 + (ln & 3) + r * 4;
        int n  = nt * 8 + (ln >> 2);
        const float* W = l ? W2 : W1;
        g_wf[l][j] = to_tf32(W[k * 128 + n]);
    }
    if (blockIdx.x == 0 && threadIdx.x < 32) {
        int lane = threadIdx.x;
        int acc = 0;
        for (int jj = 0; jj < 8; jj++) acc |= ei32[1 + 2 * (lane + 32 * jj)];
        unsigned b = __ballot_sync(0xFFFFFFFFu, acc != 0);
        if (lane == 0) g_is64 = (b == 0) ? 1 : 0;
    }
}

__global__ void k_prep(const void* __restrict__ eiv) {
    int e = blockIdx.x * blockDim.x + threadIdx.x;
    if (e >= NE) return;
    int s, d;
    if (g_is64) {
        const long long* ei = (const long long*)eiv;
        s = (int)ei[e];
        d = (int)ei[NE + e];
    } else {
        const int* ei = (const int*)eiv;
        s = ei[e];
        d = ei[NE + e];
    }
    if ((unsigned)s >= NN) s = 0;
    if ((unsigned)d >= NN) d = 0;
    g_srcd[e] = s;
    g_dstd[e] = d;
    atomicAdd(&g_deg[d], 1);
}

// fused dis + exclusive scan (98 blocks <= 148 SMs -> co-resident, spin safe)
__global__ void k_scan_all() {
    __shared__ int sh[512];
    __shared__ int s_prefix;
    int t = threadIdx.x, b = blockIdx.x;
    int i = b * 512 + t;

    int dg = 0;
    if (i < NN) {
        dg = g_deg[i];
        g_dis[i] = rsqrtf((float)(dg + 1));
    }
    sh[t] = dg;
    __syncthreads();
    for (int o = 1; o < 512; o <<= 1) {
        int a = (t >= o) ? sh[t - o] : 0;
        __syncthreads();
        sh[t] += a;
        __syncthreads();
    }
    int incl = sh[t];

    if (t == 511) {
        g_part[b] = incl;
        __threadfence();
        atomicAdd(&g_pdone, 1);
    }
    if (t == 0) {
        volatile int* p = &g_pdone;
        while (*p < NBLK) {}
    }
    __syncthreads();

    if (t < 32) {
        int s = 0;
        for (int j = t; j < b; j += 32) s += __ldcg(&g_part[j]);
#pragma unroll
        for (int o = 16; o > 0; o >>= 1) s += __shfl_down_sync(0xFFFFFFFFu, s, o);
        if (t == 0) s_prefix = s;
    }
    __syncthreads();

    if (i < NN) {
        int ex = s_prefix + incl - dg;
        g_rowptr[i] = ex;
        g_cursor[i] = ex;
    }
    if (i == 0) g_rowptr[NN] = NE;
}

__global__ void k_fill() {
    int e = blockIdx.x * blockDim.x + threadIdx.x;
    if (e >= NE) return;
    int d = g_dstd[e];
    int s = g_srcd[e];
    int pos = atomicAdd(&g_cursor[d], 1);
    if ((unsigned)pos < NE) {
        g_edge[pos] = make_int2(s, __float_as_int(g_dis[s]));
    }
}

// ---------------------------------------------------------------------------
// tf32 tensor-core GEMM: g_h[NN,128] = x[NN,128] @ W[128,128]
// 256 thr (8 warps), 64-row block tile. warp (wr=wid&3, wc=wid>>2):
//   rows [wr*16, wr*16+16), cols [wc*64, wc*64+64) -> 8 n-tiles of m16n8k8.
// A: smem, XOR-swizzled (phys f4col = c4 ^ (row&7)) -> conflict-free frag LDS.
// B: fragment-ordered g_wf, LDG.64 per fragment (64KB, L1-resident).
// ---------------------------------------------------------------------------
__global__ void k_gemm(const float* __restrict__ x_ext, int use_x1, int wsel) {
    const float* x = use_x1 ? g_x1 : x_ext;
    __shared__ float As[64 * 128];

    int t    = threadIdx.x;
    int base = blockIdx.x * 64;

    // load A tile (swizzled)
    const float4* x4 = (const float4*)x;
    for (int i = t; i < 64 * 32; i += 256) {
        int r = i >> 5, c4 = i & 31;
        int gr = base + r;
        float4 v = make_float4(0.f, 0.f, 0.f, 0.f);
        if (gr < NN) v = x4[gr * 32 + c4];
        ((float4*)As)[r * 32 + (c4 ^ (r & 7))] = v;
    }
    __syncthreads();

    int wid  = t >> 5;
    int lane = t & 31;
    int gid  = lane >> 2;       // group id (0-7)
    int tig  = lane & 3;        // thread in group (0-3)
    int wr   = wid & 3;
    int wc   = wid >> 2;

    const uint2* wf = (const uint2*)g_wf[wsel];

    float acc[8][4];
#pragma unroll
    for (int n = 0; n < 8; n++)
#pragma unroll
        for (int j = 0; j < 4; j++) acc[n][j] = 0.f;

    int rA   = wr * 16 + gid;        // local row for a0/a2 (a1/a3: +8)
    int sw   = gid << 2;             // scalar-col XOR term ((row&7)<<2)

#pragma unroll
    for (int kt = 0; kt < 16; kt++) {
        int k0 = kt * 8;
        unsigned a0 = to_tf32(As[rA * 128 + ((k0 + tig) ^ sw)]);
        unsigned a1 = to_tf32(As[(rA + 8) * 128 + ((k0 + tig) ^ sw)]);
        unsigned a2 = to_tf32(As[rA * 128 + ((k0 + tig + 4) ^ sw)]);
        unsigned a3 = to_tf32(As[(rA + 8) * 128 + ((k0 + tig + 4) ^ sw)]);
#pragma unroll
        for (int nt = 0; nt < 8; nt++) {
            uint2 b = wf[(kt * 16 + wc * 8 + nt) * 32 + lane];
            asm volatile(
                "mma.sync.aligned.m16n8k8.row.col.f32.tf32.tf32.f32 "
                "{%0,%1,%2,%3}, {%4,%5,%6,%7}, {%8,%9}, {%0,%1,%2,%3};"
                : "+f"(acc[nt][0]), "+f"(acc[nt][1]),
                  "+f"(acc[nt][2]), "+f"(acc[nt][3])
                : "r"(a0), "r"(a1), "r"(a2), "r"(a3), "r"(b.x), "r"(b.y));
        }
    }

    // epilogue: c0/c1 -> (row, col..col+1), c2/c3 -> (row+8, ...)
    int row0 = base + wr * 16 + gid;
#pragma unroll
    for (int nt = 0; nt < 8; nt++) {
        int col = wc * 64 + nt * 8 + tig * 2;
        if (row0 < NN)
            *(float2*)&g_h[row0 * 128 + col] = make_float2(acc[nt][0], acc[nt][1]);
        if (row0 + 8 < NN)
            *(float2*)&g_h[(row0 + 8) * 128 + col] = make_float2(acc[nt][2], acc[nt][3]);
    }
}

// Aggregation: one warp per node; lane holds 4 contiguous cols (float4).
__global__ void k_agg(const float* __restrict__ bias, float* __restrict__ out_ext,
                      int layer) {
    int node = blockIdx.x * (blockDim.x >> 5) + (threadIdx.x >> 5);
    if (node >= NN) return;
    int lane = threadIdx.x & 31;

    int beg = g_rowptr[node];
    int end = g_rowptr[node + 1];

    const float4* h4 = (const float4*)g_h;
    float4 acc0 = make_float4(0.f, 0.f, 0.f, 0.f);
    float4 acc1 = make_float4(0.f, 0.f, 0.f, 0.f);

    int e = beg;
    for (; e + 1 < end; e += 2) {
        int2 p0 = g_edge[e];
        int2 p1 = g_edge[e + 1];
        float c0 = __int_as_float(p0.y);
        float c1 = __int_as_float(p1.y);
        float4 v0 = h4[p0.x * 32 + lane];
        float4 v1 = h4[p1.x * 32 + lane];
        acc0.x = fmaf(c0, v0.x, acc0.x);
        acc0.y = fmaf(c0, v0.y, acc0.y);
        acc0.z = fmaf(c0, v0.z, acc0.z);
        acc0.w = fmaf(c0, v0.w, acc0.w);
        acc1.x = fmaf(c1, v1.x, acc1.x);
        acc1.y = fmaf(c1, v1.y, acc1.y);
        acc1.z = fmaf(c1, v1.z, acc1.z);
        acc1.w = fmaf(c1, v1.w, acc1.w);
    }
    if (e < end) {
        int2 p0 = g_edge[e];
        float c0 = __int_as_float(p0.y);
        float4 v0 = h4[p0.x * 32 + lane];
        acc0.x = fmaf(c0, v0.x, acc0.x);
        acc0.y = fmaf(c0, v0.y, acc0.y);
        acc0.z = fmaf(c0, v0.z, acc0.z);
        acc0.w = fmaf(c0, v0.w, acc0.w);
    }
    acc0.x += acc1.x; acc0.y += acc1.y; acc0.z += acc1.z; acc0.w += acc1.w;

    float dn = g_dis[node];
    float sn = dn * dn;
    float4 hv = h4[node * 32 + lane];
    float4 b  = ((const float4*)bias)[lane];

    float4 r;
    r.x = dn * acc0.x + sn * hv.x + b.x;
    r.y = dn * acc0.y + sn * hv.y + b.y;
    r.z = dn * acc0.z + sn * hv.z + b.z;
    r.w = dn * acc0.w + sn * hv.w + b.w;

    if (layer == 0) {
        r.x = fmaxf(r.x, 0.f);
        r.y = fmaxf(r.y, 0.f);
        r.z = fmaxf(r.z, 0.f);
        r.w = fmaxf(r.w, 0.f);
        ((float4*)g_x1)[node * 32 + lane] = r;
    } else {
        ((float4*)out_ext)[node * 32 + lane] = r;
    }
}

extern "C" void kernel_launch(void* const* d_in, const int* in_sizes, int n_in,
                              void* d_out, int out_size) {
    const void*  ei  = d_in[0];
    const float* emb = (const float*)d_in[1];
    const float* W1  = (const float*)d_in[2];
    const float* b1  = (const float*)d_in[3];
    const float* W2  = (const float*)d_in[4];
    const float* b2  = (const float*)d_in[5];
    float* out = (float*)d_out;

    (void)in_sizes; (void)n_in; (void)out_size;

    k_init<<<196, 256>>>((const int*)ei, W1, W2);   // zero+detect+wfrag
    k_prep<<<(NE + 255) / 256, 256>>>(ei);
    k_scan_all<<<NBLK, 512>>>();
    k_fill<<<(NE + 255) / 256, 256>>>();

    k_gemm<<<GBLK, 256>>>(emb, 0, 0);               // layer-1 GEMM (tf32)
    k_agg<<<(NN + 7) / 8, 256>>>(b1, out, 0);       // -> g_x1 (relu)

    k_gemm<<<GBLK, 256>>>(nullptr, 1, 1);           // layer-2 GEMM (tf32)
    k_agg<<<(NN + 7) / 8, 256>>>(b2, out, 1);       // -> d_out
}

// round 10
// speedup vs baseline: 1.6788x; 1.0440x over previous
#include <cuda_runtime.h>
#include <cuda_fp16.h>
#include <cstdint>

#define NN 50000
#define NE 800000
#define D  128
#define NBLK 98                  // ceil(50000/512) scan blocks
#define GBLK 782                 // ceil(50000/64) gemm blocks

// ---- scratch (no allocations allowed) ----
__device__ int      g_deg[NN];
__device__ int      g_rowptr[NN + 1];
__device__ int      g_cursor[NN];
__device__ int2     g_edge[NE];      // {src, dis[src] bits}
__device__ float    g_dis[NN];
__device__ __half2  g_h2[NN * 64];   // GEMM output, fp16 (128 cols = 64 half2)
__device__ float    g_x1[NN * D];    // layer-1 activation (fp32)
__device__ int      g_part[NBLK];
__device__ int      g_pdone;
__device__ int      g_is64;
__device__ unsigned g_wf[2][16384];  // fragment-ordered tf32 weights

__device__ __forceinline__ unsigned to_tf32(float f) {
    unsigned r;
    asm("cvt.rna.tf32.f32 %0, %1;" : "=r"(r) : "f"(f));
    return r;
}

__device__ __forceinline__ void decode_edge(const void* eiv, int is64, int e,
                                            int& s, int& d) {
    if (is64) {
        const long long* ei = (const long long*)eiv;
        s = (int)ei[e];
        d = (int)ei[NE + e];
    } else {
        const int* ei = (const int*)eiv;
        s = ei[e];
        d = ei[NE + e];
    }
    if ((unsigned)s >= NN) s = 0;
    if ((unsigned)d >= NN) d = 0;
}

// init: zero deg, reset scan flag, dtype-detect, build fragment-ordered tf32 W1/W2.
// wf layout: frag(kt 0..15, nt 0..15): elem = ((kt*16+nt)*32 + lane)*2 + r
//   value = tf32( W[(kt*8 + lane%4 + r*4)*128 + nt*8 + lane/4] )
__global__ void k_init(const int* __restrict__ ei32,
                       const float* __restrict__ W1,
                       const float* __restrict__ W2) {
    int i = blockIdx.x * blockDim.x + threadIdx.x;
    if (i < NN) g_deg[i] = 0;
    if (i == 0) g_pdone = 0;
    if (i < 32768) {
        int l  = (i >= 16384) ? 1 : 0;
        int j  = i & 16383;
        int r  = j & 1;
        int ln = (j >> 1) & 31;
        int nt = (j >> 6) & 15;
        int kt = j >> 10;
        int k  = kt * 8 + (ln & 3) + r * 4;
        int n  = nt * 8 + (ln >> 2);
        const float* W = l ? W2 : W1;
        g_wf[l][j] = to_tf32(W[k * 128 + n]);
    }
    if (blockIdx.x == 0 && threadIdx.x < 32) {
        int lane = threadIdx.x;
        int acc = 0;
        for (int jj = 0; jj < 8; jj++) acc |= ei32[1 + 2 * (lane + 32 * jj)];
        unsigned b = __ballot_sync(0xFFFFFFFFu, acc != 0);
        if (lane == 0) g_is64 = (b == 0) ? 1 : 0;
    }
}

__global__ void k_prep(const void* __restrict__ eiv) {
    int e = blockIdx.x * blockDim.x + threadIdx.x;
    if (e >= NE) return;
    int s, d;
    decode_edge(eiv, g_is64, e, s, d);
    atomicAdd(&g_deg[d], 1);
}

// fused dis + exclusive scan (98 blocks <= 148 SMs -> co-resident, spin safe)
__global__ void k_scan_all() {
    __shared__ int sh[512];
    __shared__ int s_prefix;
    int t = threadIdx.x, b = blockIdx.x;
    int i = b * 512 + t;

    int dg = 0;
    if (i < NN) {
        dg = g_deg[i];
        g_dis[i] = rsqrtf((float)(dg + 1));
    }
    sh[t] = dg;
    __syncthreads();
    for (int o = 1; o < 512; o <<= 1) {
        int a = (t >= o) ? sh[t - o] : 0;
        __syncthreads();
        sh[t] += a;
        __syncthreads();
    }
    int incl = sh[t];

    if (t == 511) {
        g_part[b] = incl;
        __threadfence();
        atomicAdd(&g_pdone, 1);
    }
    if (t == 0) {
        volatile int* p = &g_pdone;
        while (*p < NBLK) {}
    }
    __syncthreads();

    if (t < 32) {
        int s = 0;
        for (int j = t; j < b; j += 32) s += __ldcg(&g_part[j]);
#pragma unroll
        for (int o = 16; o > 0; o >>= 1) s += __shfl_down_sync(0xFFFFFFFFu, s, o);
        if (t == 0) s_prefix = s;
    }
    __syncthreads();

    if (i < NN) {
        int ex = s_prefix + incl - dg;
        g_rowptr[i] = ex;
        g_cursor[i] = ex;
    }
    if (i == 0) g_rowptr[NN] = NE;
}

__global__ void k_fill(const void* __restrict__ eiv) {
    int e = blockIdx.x * blockDim.x + threadIdx.x;
    if (e >= NE) return;
    int s, d;
    decode_edge(eiv, g_is64, e, s, d);
    int pos = atomicAdd(&g_cursor[d], 1);
    if ((unsigned)pos < NE) {
        g_edge[pos] = make_int2(s, __float_as_int(g_dis[s]));
    }
}

// ---------------------------------------------------------------------------
// tf32 tensor-core GEMM: g_h2[NN,128](fp16) = x[NN,128] @ W[128,128]
// 256 thr (8 warps), 64-row tile. warp (wr=wid&3, wc=wid>>2):
//   rows [wr*16,+16), cols [wc*64,+64) -> 8 n-tiles of m16n8k8.
// A: smem XOR-swizzled; B: fragment-ordered g_wf (L1-resident LDG.64).
// ---------------------------------------------------------------------------
__global__ void k_gemm(const float* __restrict__ x_ext, int use_x1, int wsel) {
    const float* x = use_x1 ? g_x1 : x_ext;
    __shared__ float As[64 * 128];

    int t    = threadIdx.x;
    int base = blockIdx.x * 64;

    const float4* x4 = (const float4*)x;
    for (int i = t; i < 64 * 32; i += 256) {
        int r = i >> 5, c4 = i & 31;
        int gr = base + r;
        float4 v = make_float4(0.f, 0.f, 0.f, 0.f);
        if (gr < NN) v = x4[gr * 32 + c4];
        ((float4*)As)[r * 32 + (c4 ^ (r & 7))] = v;
    }
    __syncthreads();

    int wid  = t >> 5;
    int lane = t & 31;
    int gid  = lane >> 2;
    int tig  = lane & 3;
    int wr   = wid & 3;
    int wc   = wid >> 2;

    const uint2* wf = (const uint2*)g_wf[wsel];

    float acc[8][4];
#pragma unroll
    for (int n = 0; n < 8; n++)
#pragma unroll
        for (int j = 0; j < 4; j++) acc[n][j] = 0.f;

    int rA = wr * 16 + gid;
    int sw = gid << 2;

#pragma unroll
    for (int kt = 0; kt < 16; kt++) {
        int k0 = kt * 8;
        unsigned a0 = to_tf32(As[rA * 128 + ((k0 + tig) ^ sw)]);
        unsigned a1 = to_tf32(As[(rA + 8) * 128 + ((k0 + tig) ^ sw)]);
        unsigned a2 = to_tf32(As[rA * 128 + ((k0 + tig + 4) ^ sw)]);
        unsigned a3 = to_tf32(As[(rA + 8) * 128 + ((k0 + tig + 4) ^ sw)]);
#pragma unroll
        for (int nt = 0; nt < 8; nt++) {
            uint2 b = wf[(kt * 16 + wc * 8 + nt) * 32 + lane];
            asm volatile(
                "mma.sync.aligned.m16n8k8.row.col.f32.tf32.tf32.f32 "
                "{%0,%1,%2,%3}, {%4,%5,%6,%7}, {%8,%9}, {%0,%1,%2,%3};"
                : "+f"(acc[nt][0]), "+f"(acc[nt][1]),
                  "+f"(acc[nt][2]), "+f"(acc[nt][3])
                : "r"(a0), "r"(a1), "r"(a2), "r"(a3), "r"(b.x), "r"(b.y));
        }
    }

    // epilogue: fp16 store. c0/c1 -> (row, col..col+1), c2/c3 -> (row+8, ...)
    int row0 = base + wr * 16 + gid;
#pragma unroll
    for (int nt = 0; nt < 8; nt++) {
        int c2i = wc * 32 + nt * 4 + tig;      // half2 index of cols (2*c2i, 2*c2i+1)
        if (row0 < NN)
            g_h2[row0 * 64 + c2i] = __floats2half2_rn(acc[nt][0], acc[nt][1]);
        if (row0 + 8 < NN)
            g_h2[(row0 + 8) * 64 + c2i] = __floats2half2_rn(acc[nt][2], acc[nt][3]);
    }
}

// Aggregation: one warp per node; lane holds 4 contiguous cols (2×half2 = 8B gather).
// out[d] = dis[d] * sum_e( dis[src_e]*h[src_e] ) + dis[d]^2 * h[d] + bias
__global__ void k_agg(const float* __restrict__ bias, float* __restrict__ out_ext,
                      int layer) {
    int node = blockIdx.x * (blockDim.x >> 5) + (threadIdx.x >> 5);
    if (node >= NN) return;
    int lane = threadIdx.x & 31;

    int beg = g_rowptr[node];
    int end = g_rowptr[node + 1];

    const uint2* h8 = (const uint2*)g_h2;   // 4 halves per lane
    float4 acc0 = make_float4(0.f, 0.f, 0.f, 0.f);
    float4 acc1 = make_float4(0.f, 0.f, 0.f, 0.f);

    int e = beg;
    for (; e + 1 < end; e += 2) {
        int2 p0 = g_edge[e];
        int2 p1 = g_edge[e + 1];
        float c0 = __int_as_float(p0.y);
        float c1 = __int_as_float(p1.y);
        uint2 u0 = h8[p0.x * 32 + lane];
        uint2 u1 = h8[p1.x * 32 + lane];
        float2 a0 = __half22float2(*(const __half2*)&u0.x);
        float2 b0 = __half22float2(*(const __half2*)&u0.y);
        float2 a1 = __half22float2(*(const __half2*)&u1.x);
        float2 b1 = __half22float2(*(const __half2*)&u1.y);
        acc0.x = fmaf(c0, a0.x, acc0.x);
        acc0.y = fmaf(c0, a0.y, acc0.y);
        acc0.z = fmaf(c0, b0.x, acc0.z);
        acc0.w = fmaf(c0, b0.y, acc0.w);
        acc1.x = fmaf(c1, a1.x, acc1.x);
        acc1.y = fmaf(c1, a1.y, acc1.y);
        acc1.z = fmaf(c1, b1.x, acc1.z);
        acc1.w = fmaf(c1, b1.y, acc1.w);
    }
    if (e < end) {
        int2 p0 = g_edge[e];
        float c0 = __int_as_float(p0.y);
        uint2 u0 = h8[p0.x * 32 + lane];
        float2 a0 = __half22float2(*(const __half2*)&u0.x);
        float2 b0 = __half22float2(*(const __half2*)&u0.y);
        acc0.x = fmaf(c0, a0.x, acc0.x);
        acc0.y = fmaf(c0, a0.y, acc0.y);
        acc0.z = fmaf(c0, b0.x, acc0.z);
        acc0.w = fmaf(c0, b0.y, acc0.w);
    }
    acc0.x += acc1.x; acc0.y += acc1.y; acc0.z += acc1.z; acc0.w += acc1.w;

    float dn = g_dis[node];
    float sn = dn * dn;
    uint2 uh = h8[node * 32 + lane];
    float2 ha = __half22float2(*(const __half2*)&uh.x);
    float2 hb = __half22float2(*(const __half2*)&uh.y);
    float4 b  = ((const float4*)bias)[lane];

    float4 r;
    r.x = dn * acc0.x + sn * ha.x + b.x;
    r.y = dn * acc0.y + sn * ha.y + b.y;
    r.z = dn * acc0.z + sn * hb.x + b.z;
    r.w = dn * acc0.w + sn * hb.y + b.w;

    if (layer == 0) {
        r.x = fmaxf(r.x, 0.f);
        r.y = fmaxf(r.y, 0.f);
        r.z = fmaxf(r.z, 0.f);
        r.w = fmaxf(r.w, 0.f);
        ((float4*)g_x1)[node * 32 + lane] = r;
    } else {
        ((float4*)out_ext)[node * 32 + lane] = r;
    }
}

extern "C" void kernel_launch(void* const* d_in, const int* in_sizes, int n_in,
                              void* d_out, int out_size) {
    const void*  ei  = d_in[0];
    const float* emb = (const float*)d_in[1];
    const float* W1  = (const float*)d_in[2];
    const float* b1  = (const float*)d_in[3];
    const float* W2  = (const float*)d_in[4];
    const float* b2  = (const float*)d_in[5];
    float* out = (float*)d_out;

    (void)in_sizes; (void)n_in; (void)out_size;

    k_init<<<196, 256>>>((const int*)ei, W1, W2);   // zero+detect+wfrag
    k_prep<<<(NE + 255) / 256, 256>>>(ei);
    k_scan_all<<<NBLK, 512>>>();
    k_fill<<<(NE + 255) / 256, 256>>>(ei);

    k_gemm<<<GBLK, 256>>>(emb, 0, 0);               // layer-1 GEMM (tf32 -> fp16 h)
    k_agg<<<(NN + 7) / 8, 256>>>(b1, out, 0);       // -> g_x1 (relu, fp32)

    k_gemm<<<GBLK, 256>>>(nullptr, 1, 1);           // layer-2 GEMM
    k_agg<<<(NN + 7) / 8, 256>>>(b2, out, 1);       // -> d_out
}

// round 11
// speedup vs baseline: 1.7877x; 1.0649x over previous
#include <cuda_runtime.h>
#include <cuda_fp16.h>
#include <cstdint>

#define NN 50000
#define NE 800000
#define D  128
#define NBLK 98                  // ceil(50000/512) scan blocks
#define GBLK 782                 // ceil(50000/64) gemm blocks

// ---- scratch (no allocations allowed) ----
__device__ int      g_deg[NN];
__device__ int      g_rowptr[NN + 1];
__device__ int      g_srcd[NE];      // staged src
__device__ int      g_dstd[NE];      // staged dst
__device__ int      g_pos[NE];       // staged within-dst slot
__device__ int2     g_edge[NE];      // CSR: {src, dis[src] bits}
__device__ float    g_dis[NN];
__device__ __half2  g_h2[NN * 64];   // GEMM output, fp16 (128 cols = 64 half2)
__device__ float    g_x1[NN * D];    // layer-1 activation (fp32)
__device__ int      g_part[NBLK];
__device__ int      g_pdone;
__device__ int      g_is64;
__device__ unsigned g_wf[2][16384];  // fragment-ordered tf32 weights

__device__ __forceinline__ unsigned to_tf32(float f) {
    unsigned r;
    asm("cvt.rna.tf32.f32 %0, %1;" : "=r"(r) : "f"(f));
    return r;
}

// init: zero deg, reset scan flag, dtype-detect, build fragment-ordered tf32 W1/W2.
__global__ void k_init(const int* __restrict__ ei32,
                       const float* __restrict__ W1,
                       const float* __restrict__ W2) {
    int i = blockIdx.x * blockDim.x + threadIdx.x;
    if (i < NN) g_deg[i] = 0;
    if (i == 0) g_pdone = 0;
    if (i < 32768) {
        int l  = (i >= 16384) ? 1 : 0;
        int j  = i & 16383;
        int r  = j & 1;
        int ln = (j >> 1) & 31;
        int nt = (j >> 6) & 15;
        int kt = j >> 10;
        int k  = kt * 8 + (ln & 3) + r * 4;
        int n  = nt * 8 + (ln >> 2);
        const float* W = l ? W2 : W1;
        g_wf[l][j] = to_tf32(W[k * 128 + n]);
    }
    if (blockIdx.x == 0 && threadIdx.x < 32) {
        int lane = threadIdx.x;
        int acc = 0;
        for (int jj = 0; jj < 8; jj++) acc |= ei32[1 + 2 * (lane + 32 * jj)];
        unsigned b = __ballot_sync(0xFFFFFFFFu, acc != 0);
        if (lane == 0) g_is64 = (b == 0) ? 1 : 0;
    }
}

// decode + degree-count + slot assignment (single atomic pass over edges)
__global__ void k_prep(const void* __restrict__ eiv) {
    int e = blockIdx.x * blockDim.x + threadIdx.x;
    if (e >= NE) return;
    int s, d;
    if (g_is64) {
        const long long* ei = (const long long*)eiv;
        s = (int)ei[e];
        d = (int)ei[NE + e];
    } else {
        const int* ei = (const int*)eiv;
        s = ei[e];
        d = ei[NE + e];
    }
    if ((unsigned)s >= NN) s = 0;
    if ((unsigned)d >= NN) d = 0;
    int pos = atomicAdd(&g_deg[d], 1);
    g_srcd[e] = s;
    g_dstd[e] = d;
    g_pos[e]  = pos;
}

// fused dis + exclusive scan (98 blocks <= 148 SMs -> co-resident, spin safe)
__global__ void k_scan_all() {
    __shared__ int sh[512];
    __shared__ int s_prefix;
    int t = threadIdx.x, b = blockIdx.x;
    int i = b * 512 + t;

    int dg = 0;
    if (i < NN) {
        dg = g_deg[i];
        g_dis[i] = rsqrtf((float)(dg + 1));
    }
    sh[t] = dg;
    __syncthreads();
    for (int o = 1; o < 512; o <<= 1) {
        int a = (t >= o) ? sh[t - o] : 0;
        __syncthreads();
        sh[t] += a;
        __syncthreads();
    }
    int incl = sh[t];

    if (t == 511) {
        g_part[b] = incl;
        __threadfence();
        atomicAdd(&g_pdone, 1);
    }
    if (t == 0) {
        volatile int* p = &g_pdone;
        while (*p < NBLK) {}
    }
    __syncthreads();

    if (t < 32) {
        int s = 0;
        for (int j = t; j < b; j += 32) s += __ldcg(&g_part[j]);
#pragma unroll
        for (int o = 16; o > 0; o >>= 1) s += __shfl_down_sync(0xFFFFFFFFu, s, o);
        if (t == 0) s_prefix = s;
    }
    __syncthreads();

    if (i < NN) g_rowptr[i] = s_prefix + incl - dg;   // exclusive
    if (i == 0) g_rowptr[NN] = NE;
}

// atomic-free CSR fill: pure staged-read -> scatter-write
__global__ void k_fill() {
    int e = blockIdx.x * blockDim.x + threadIdx.x;
    if (e >= NE) return;
    int s   = g_srcd[e];
    int d   = g_dstd[e];
    int pos = g_pos[e];
    g_edge[g_rowptr[d] + pos] = make_int2(s, __float_as_int(g_dis[s]));
}

// ---------------------------------------------------------------------------
// tf32 tensor-core GEMM: g_h2[NN,128](fp16) = x[NN,128] @ W[128,128]
// ---------------------------------------------------------------------------
__global__ void k_gemm(const float* __restrict__ x_ext, int use_x1, int wsel) {
    const float* x = use_x1 ? g_x1 : x_ext;
    __shared__ float As[64 * 128];

    int t    = threadIdx.x;
    int base = blockIdx.x * 64;

    const float4* x4 = (const float4*)x;
    for (int i = t; i < 64 * 32; i += 256) {
        int r = i >> 5, c4 = i & 31;
        int gr = base + r;
        float4 v = make_float4(0.f, 0.f, 0.f, 0.f);
        if (gr < NN) v = x4[gr * 32 + c4];
        ((float4*)As)[r * 32 + (c4 ^ (r & 7))] = v;
    }
    __syncthreads();

    int wid  = t >> 5;
    int lane = t & 31;
    int gid  = lane >> 2;
    int tig  = lane & 3;
    int wr   = wid & 3;
    int wc   = wid >> 2;

    const uint2* wf = (const uint2*)g_wf[wsel];

    float acc[8][4];
#pragma unroll
    for (int n = 0; n < 8; n++)
#pragma unroll
        for (int j = 0; j < 4; j++) acc[n][j] = 0.f;

    int rA = wr * 16 + gid;
    int sw = gid << 2;

#pragma unroll
    for (int kt = 0; kt < 16; kt++) {
        int k0 = kt * 8;
        unsigned a0 = to_tf32(As[rA * 128 + ((k0 + tig) ^ sw)]);
        unsigned a1 = to_tf32(As[(rA + 8) * 128 + ((k0 + tig) ^ sw)]);
        unsigned a2 = to_tf32(As[rA * 128 + ((k0 + tig + 4) ^ sw)]);
        unsigned a3 = to_tf32(As[(rA + 8) * 128 + ((k0 + tig + 4) ^ sw)]);
#pragma unroll
        for (int nt = 0; nt < 8; nt++) {
            uint2 b = wf[(kt * 16 + wc * 8 + nt) * 32 + lane];
            asm volatile(
                "mma.sync.aligned.m16n8k8.row.col.f32.tf32.tf32.f32 "
                "{%0,%1,%2,%3}, {%4,%5,%6,%7}, {%8,%9}, {%0,%1,%2,%3};"
                : "+f"(acc[nt][0]), "+f"(acc[nt][1]),
                  "+f"(acc[nt][2]), "+f"(acc[nt][3])
                : "r"(a0), "r"(a1), "r"(a2), "r"(a3), "r"(b.x), "r"(b.y));
        }
    }

    int row0 = base + wr * 16 + gid;
#pragma unroll
    for (int nt = 0; nt < 8; nt++) {
        int c2i = wc * 32 + nt * 4 + tig;
        if (row0 < NN)
            g_h2[row0 * 64 + c2i] = __floats2half2_rn(acc[nt][0], acc[nt][1]);
        if (row0 + 8 < NN)
            g_h2[(row0 + 8) * 64 + c2i] = __floats2half2_rn(acc[nt][2], acc[nt][3]);
    }
}

__device__ __forceinline__ void agg_fma(float4& a, float c, uint2 u) {
    float2 lo = __half22float2(*(const __half2*)&u.x);
    float2 hi = __half22float2(*(const __half2*)&u.y);
    a.x = fmaf(c, lo.x, a.x);
    a.y = fmaf(c, lo.y, a.y);
    a.z = fmaf(c, hi.x, a.z);
    a.w = fmaf(c, hi.y, a.w);
}

// Aggregation: one warp per node; lane = 4 cols (8B gather). MLP=4 mainloop.
__global__ void k_agg(const float* __restrict__ bias, float* __restrict__ out_ext,
                      int layer) {
    int node = blockIdx.x * (blockDim.x >> 5) + (threadIdx.x >> 5);
    if (node >= NN) return;
    int lane = threadIdx.x & 31;

    int beg = g_rowptr[node];
    int end = g_rowptr[node + 1];

    const uint2* h8 = (const uint2*)g_h2;
    float4 A0 = make_float4(0.f, 0.f, 0.f, 0.f);
    float4 A1 = make_float4(0.f, 0.f, 0.f, 0.f);
    float4 A2 = make_float4(0.f, 0.f, 0.f, 0.f);
    float4 A3 = make_float4(0.f, 0.f, 0.f, 0.f);

    int e = beg;
    for (; e + 3 < end; e += 4) {
        int2 p0 = g_edge[e];
        int2 p1 = g_edge[e + 1];
        int2 p2 = g_edge[e + 2];
        int2 p3 = g_edge[e + 3];
        uint2 u0 = h8[p0.x * 32 + lane];
        uint2 u1 = h8[p1.x * 32 + lane];
        uint2 u2 = h8[p2.x * 32 + lane];
        uint2 u3 = h8[p3.x * 32 + lane];
        agg_fma(A0, __int_as_float(p0.y), u0);
        agg_fma(A1, __int_as_float(p1.y), u1);
        agg_fma(A2, __int_as_float(p2.y), u2);
        agg_fma(A3, __int_as_float(p3.y), u3);
    }
    if (e + 1 < end) {
        int2 p0 = g_edge[e];
        int2 p1 = g_edge[e + 1];
        uint2 u0 = h8[p0.x * 32 + lane];
        uint2 u1 = h8[p1.x * 32 + lane];
        agg_fma(A0, __int_as_float(p0.y), u0);
        agg_fma(A1, __int_as_float(p1.y), u1);
        e += 2;
    }
    if (e < end) {
        int2 p0 = g_edge[e];
        uint2 u0 = h8[p0.x * 32 + lane];
        agg_fma(A0, __int_as_float(p0.y), u0);
    }
    A0.x += A1.x + A2.x + A3.x;
    A0.y += A1.y + A2.y + A3.y;
    A0.z += A1.z + A2.z + A3.z;
    A0.w += A1.w + A2.w + A3.w;

    float dn = g_dis[node];
    float sn = dn * dn;
    uint2 uh = h8[node * 32 + lane];
    float2 ha = __half22float2(*(const __half2*)&uh.x);
    float2 hb = __half22float2(*(const __half2*)&uh.y);
    float4 b  = ((const float4*)bias)[lane];

    float4 r;
    r.x = dn * A0.x + sn * ha.x + b.x;
    r.y = dn * A0.y + sn * ha.y + b.y;
    r.z = dn * A0.z + sn * hb.x + b.z;
    r.w = dn * A0.w + sn * hb.y + b.w;

    if (layer == 0) {
        r.x = fmaxf(r.x, 0.f);
        r.y = fmaxf(r.y, 0.f);
        r.z = fmaxf(r.z, 0.f);
        r.w = fmaxf(r.w, 0.f);
        ((float4*)g_x1)[node * 32 + lane] = r;
    } else {
        ((float4*)out_ext)[node * 32 + lane] = r;
    }
}

extern "C" void kernel_launch(void* const* d_in, const int* in_sizes, int n_in,
                              void* d_out, int out_size) {
    const void*  ei  = d_in[0];
    const float* emb = (const float*)d_in[1];
    const float* W1  = (const float*)d_in[2];
    const float* b1  = (const float*)d_in[3];
    const float* W2  = (const float*)d_in[4];
    const float* b2  = (const float*)d_in[5];
    float* out = (float*)d_out;

    (void)in_sizes; (void)n_in; (void)out_size;

    k_init<<<196, 256>>>((const int*)ei, W1, W2);   // zero+detect+wfrag
    k_prep<<<(NE + 255) / 256, 256>>>(ei);          // decode+count+slot (1 atomic pass)
    k_scan_all<<<NBLK, 512>>>();                    // dis + exclusive scan
    k_fill<<<(NE + 255) / 256, 256>>>();            // atomic-free scatter

    k_gemm<<<GBLK, 256>>>(emb, 0, 0);               // layer-1 GEMM (tf32 -> fp16 h)
    k_agg<<<(NN + 7) / 8, 256>>>(b1, out, 0);       // -> g_x1 (relu, fp32)

    k_gemm<<<GBLK, 256>>>(nullptr, 1, 1);           // layer-2 GEMM
    k_agg<<<(NN + 7) / 8, 256>>>(b2, out, 1);       // -> d_out
}